// round 15
// baseline (speedup 1.0000x reference)
#include <cuda_runtime.h>
#include <cuda_fp16.h>
#include <cstdint>

#define IN_F   512
#define OUT_F  512
#define BATCH  16384
#define BM     128
#define BN     128
#define NSTEP  72            // 8 silu chunks + 64 spline chunks, all fp16 single-pass
#define TILE   16384         // 128 rows x 128B (64 fp16 K-slots)
#define RB_BYTES (NSTEP * TILE)           // 1.125 MB per rowblock
#define DYN    (6 * TILE + 1024)          // 3 A-buf + 3 B-buf = 97 KB

#define PACK_BLOCKS   (NSTEP * OUT_F * 64 / 256)   // 9216
#define SPLINE_BLOCKS (BATCH * IN_F / 256)         // 32768

__device__ char g_A[(size_t)128 * RB_BYTES];        // 144 MB augmented activations
__device__ char g_W[(size_t)NSTEP * OUT_F * 128];   // 4.7 MB packed fp16 weights

// ---------------- helpers ----------------
static __device__ __forceinline__ uint32_t smem_u32(const void* p) {
    uint32_t a;
    asm("{ .reg .u64 t; cvta.to.shared.u64 t, %1; cvt.u32.u64 %0, t; }" : "=r"(a) : "l"(p));
    return a;
}
static __device__ __forceinline__ void cp16(uint32_t dst, const void* src) {
    asm volatile("cp.async.cg.shared.global [%0], [%1], 16;" :: "r"(dst), "l"(src) : "memory");
}
#define CP_COMMIT() asm volatile("cp.async.commit_group;" ::: "memory")
#define CP_WAIT1()  asm volatile("cp.async.wait_group 1;" ::: "memory")

static __device__ __forceinline__ void ldsm4(uint32_t* r, uint32_t a) {
    asm volatile("ldmatrix.sync.aligned.m8n8.x4.shared.b16 {%0,%1,%2,%3}, [%4];"
                 : "=r"(r[0]), "=r"(r[1]), "=r"(r[2]), "=r"(r[3]) : "r"(a));
}
static __device__ __forceinline__ void mma_f16(float* d, const uint32_t* a, const uint32_t* b) {
    asm volatile("mma.sync.aligned.m16n8k16.row.col.f32.f16.f16.f32 "
                 "{%0,%1,%2,%3}, {%4,%5,%6,%7}, {%8,%9}, {%0,%1,%2,%3};"
                 : "+f"(d[0]), "+f"(d[1]), "+f"(d[2]), "+f"(d[3])
                 : "r"(a[0]), "r"(a[1]), "r"(a[2]), "r"(a[3]), "r"(b[0]), "r"(b[1]));
}
static __device__ __forceinline__ uint32_t pk2h(float lo, float hi) {   // low half = lo
    uint32_t r; asm("cvt.rn.f16x2.f32 %0, %1, %2;" : "=r"(r) : "f"(hi), "f"(lo)); return r;
}
static __device__ __forceinline__ uint32_t swz(uint32_t byteoff) {
    return byteoff ^ ((byteoff >> 3) & 0x70);
}
// silu via single-MUFU tanh approx: silu(x) = 0.5x * (1 + tanh(x/2))
static __device__ __forceinline__ float silu_fast(float x) {
    float th;
    asm("tanh.approx.f32 %0, %1;" : "=f"(th) : "f"(0.5f * x));
    float hx = 0.5f * x;
    return fmaf(hx, th, hx);
}

// ---------------- fused prep (single pass over x) ----------------
// blocks [0, PACK)   : pack weights (fp16, pre-swizzled)
// blocks [PACK, ...) : spline (half2 math) + silu, store-coalesced
__global__ __launch_bounds__(256)
void prep(const float* __restrict__ bw, const float* __restrict__ sw,
          const float* __restrict__ sc, const float* __restrict__ x,
          const float* __restrict__ grid) {
    if (blockIdx.x < PACK_BLOCKS) {
        int idx = blockIdx.x * 256 + threadIdx.x;
        int st = idx >> 15, r = idx & 32767;
        int n = r >> 6, slot = r & 63;
        float w;
        if (st < 8) {
            w = bw[n * IN_F + st * 64 + slot];
        } else {
            int c = st - 8;
            int k = c * 8 + (slot >> 3), j = slot & 7;
            w = sw[((size_t)n * IN_F + k) * 8 + j] * sc[n * IN_F + k];
        }
        *(__half*)(g_W + (size_t)st * 65536 + swz((unsigned)(n * 128 + slot * 2))) =
            __float2half_rn(w);
        return;
    }

    // warp -> (chunk c, 4 consecutive rows); lane -> (row, one feature)
    int idx = (blockIdx.x - PACK_BLOCKS) * 256 + threadIdx.x;   // 16384 * 512
    int w = idx >> 5, l = idx & 31;
    int c = w & 63, rg = w >> 6;                  // chunk, row-group
    int m = rg * 4 + (l >> 3);                    // global row
    int ff = l & 7;                               // feature within chunk
    int rb = m >> 7, row = m & 127;

    const float g0 = grid[0];
    const float invh = 1.0f / (grid[1] - grid[0]);

    char* Arb = g_A + (size_t)rb * RB_BYTES;
    float xv = x[(size_t)m * IN_F + c * 8 + ff];

    // ---- spline bases via half2 math: N3(s) = (m^3 - 4 d^3)/6,
    //      m = clamp(min(s, 4-s), 0), d = max(m-1, 0); 4 pairs of bases ----
    float uu = (xv - g0) * invh;
    const __half2 uu2   = __float2half2_rn(uu);
    const __half2 four  = __floats2half2_rn(4.0f, 4.0f);
    const __half2 one   = __floats2half2_rn(1.0f, 1.0f);
    const __half2 zero  = __floats2half2_rn(0.0f, 0.0f);
    const __half2 neg4  = __floats2half2_rn(-4.0f, -4.0f);
    const __half2 sixth = __floats2half2_rn(1.0f / 6.0f, 1.0f / 6.0f);

    uint32_t rr[4];
#pragma unroll
    for (int p = 0; p < 4; p++) {
        __half2 off = __floats2half2_rn((float)(2 * p), (float)(2 * p + 1));
        __half2 s  = __hsub2(uu2, off);
        __half2 mm = __hmax2(__hmin2(s, __hsub2(four, s)), zero);
        __half2 dd = __hmax2(__hsub2(mm, one), zero);
        __half2 m3 = __hmul2(__hmul2(mm, mm), mm);
        __half2 d3 = __hmul2(__hmul2(dd, dd), dd);
        __half2 res = __hmul2(__hfma2(d3, neg4, m3), sixth);
        rr[p] = *(uint32_t*)&res;
    }
    *(uint4*)(Arb + (8 + c) * TILE + swz((unsigned)(row * 128 + ff * 16))) =
        make_uint4(rr[0], rr[1], rr[2], rr[3]);

    // silu: one fp16 into silu chunk c>>3, slot (c&7)*8+ff (swizzle const over 16B group)
    unsigned sbase = swz((unsigned)(row * 128 + (c & 7) * 16));
    *(__half*)(Arb + (c >> 3) * TILE + sbase + ff * 2) = __float2half_rn(silu_fast(xv));
}

// ---------------- main kernel: uniform streaming fp16 GEMM (R10/R13, unchanged) ----------------
__global__ __launch_bounds__(256, 2)
void kan_mma(float* __restrict__ out) {
    extern __shared__ char dynraw[];
    const int tid = threadIdx.x;
    const int rb = blockIdx.y;
    const int m0 = rb * BM;
    const int n0 = blockIdx.x * BN;

    uint32_t sbase = (smem_u32(dynraw) + 1023u) & ~1023u;
    const uint32_t A0 = sbase,          A1 = sbase + TILE,     A2 = sbase + 2 * TILE;
    const uint32_t B0 = sbase + 3*TILE, B1 = sbase + 4 * TILE, B2 = sbase + 5 * TILE;

    const int l = tid & 31, wid = tid >> 5;
    const int wm = wid & 1, wn = wid >> 1;     // warp tile 64 x 32

    uint32_t offA[4], swzA[4];
#pragma unroll
    for (int mt = 0; mt < 4; mt++) {
        int rA = wm * 64 + mt * 16 + (l & 7) + (((l >> 3) & 1) << 3);
        offA[mt] = (uint32_t)(rA * 128);
        swzA[mt] = (uint32_t)((rA & 7) << 4);
    }
    const uint32_t colAsub = (uint32_t)((l >> 4) << 4);
    uint32_t offB[2], swzB[2];
#pragma unroll
    for (int nt2 = 0; nt2 < 2; nt2++) {
        int rB = wn * 32 + nt2 * 16 + (l & 7) + ((l >> 4) << 3);
        offB[nt2] = (uint32_t)(rB * 128);
        swzB[nt2] = (uint32_t)((rB & 7) << 4);
    }
    const uint32_t colBsub = (uint32_t)(((l >> 3) & 1) << 4);

    const char* Aglob = g_A + (size_t)rb * RB_BYTES;
    const char* Bglob = g_W + (size_t)n0 * 128;

    float acc[4][4][4];
#pragma unroll
    for (int a = 0; a < 4; a++)
#pragma unroll
        for (int b = 0; b < 4; b++)
#pragma unroll
            for (int c = 0; c < 4; c++) acc[a][b][c] = 0.0f;

    const uint32_t t16 = (uint32_t)(tid * 16);

    auto step = [&](int s, uint32_t Ab, uint32_t Bb, uint32_t Ad2, uint32_t Bd2) {
        CP_WAIT1();
        __syncthreads();

        const bool pf = (s + 2 < NSTEP);
        const char* As2 = Aglob + (size_t)(s + 2) * TILE;
        const char* Bs2 = Bglob + (size_t)(s + 2) * 65536;

#pragma unroll
        for (int ks = 0; ks < 4; ks++) {
            uint32_t af[4][4];
#pragma unroll
            for (int mt = 0; mt < 4; mt++)
                ldsm4(af[mt], Ab + offA[mt] + ((ks * 32 + colAsub) ^ swzA[mt]));
            uint32_t bf[4][2];
#pragma unroll
            for (int nt2 = 0; nt2 < 2; nt2++) {
                uint32_t r[4];
                ldsm4(r, Bb + offB[nt2] + ((ks * 32 + colBsub) ^ swzB[nt2]));
                bf[2 * nt2][0] = r[0]; bf[2 * nt2][1] = r[1];
                bf[2 * nt2 + 1][0] = r[2]; bf[2 * nt2 + 1][1] = r[3];
            }
#pragma unroll
            for (int mt = 0; mt < 4; mt++)
#pragma unroll
                for (int nt = 0; nt < 4; nt++)
                    mma_f16(acc[mt][nt], af[mt], bf[nt]);

            if (ks == 0 && pf) {
#pragma unroll
                for (int it = 0; it < 4; it++)
                    cp16(Ad2 + t16 + it * 4096, As2 + t16 + it * 4096);
            }
            if (ks == 1 && pf) {
#pragma unroll
                for (int it = 0; it < 4; it++)
                    cp16(Bd2 + t16 + it * 4096, Bs2 + t16 + it * 4096);
            }
        }
        CP_COMMIT();
    };

    // prologue: load steps 0, 1
    {
        const char* As = Aglob;
        const char* Bs = Bglob;
#pragma unroll
        for (int it = 0; it < 4; it++) {
            cp16(A0 + t16 + it * 4096, As + t16 + it * 4096);
            cp16(B0 + t16 + it * 4096, Bs + t16 + it * 4096);
        }
        CP_COMMIT();
        As += TILE; Bs += 65536;
#pragma unroll
        for (int it = 0; it < 4; it++) {
            cp16(A1 + t16 + it * 4096, As + t16 + it * 4096);
            cp16(B1 + t16 + it * 4096, Bs + t16 + it * 4096);
        }
        CP_COMMIT();
    }

    for (int s = 0; s < NSTEP; s += 3) {
        step(s,     A0, B0, A2, B2);
        step(s + 1, A1, B1, A0, B0);
        step(s + 2, A2, B2, A1, B1);
    }

    // ---- epilogue ----
#pragma unroll
    for (int mt = 0; mt < 4; mt++) {
#pragma unroll
        for (int nt = 0; nt < 4; nt++) {
            int m = m0 + wm * 64 + mt * 16 + (l >> 2);
            int n = n0 + wn * 32 + nt * 8 + (l & 3) * 2;
            *(float2*)(out + (size_t)m * OUT_F + n) = make_float2(acc[mt][nt][0], acc[mt][nt][1]);
            *(float2*)(out + (size_t)(m + 8) * OUT_F + n) = make_float2(acc[mt][nt][2], acc[mt][nt][3]);
        }
    }
}

extern "C" void kernel_launch(void* const* d_in, const int* in_sizes, int n_in,
                              void* d_out, int out_size) {
    const float* x    = (const float*)d_in[0];
    const float* bw   = (const float*)d_in[1];
    const float* sw   = (const float*)d_in[2];
    const float* sc   = (const float*)d_in[3];
    const float* grid = (const float*)d_in[4];
    float*       out  = (float*)d_out;

    cudaFuncSetAttribute(kan_mma, cudaFuncAttributeMaxDynamicSharedMemorySize, DYN);

    prep<<<PACK_BLOCKS + SPLINE_BLOCKS, 256>>>(bw, sw, sc, x, grid);

    dim3 g(OUT_F / BN, BATCH / BM);   // (4, 128) = 512 CTAs
    kan_mma<<<g, 256, DYN>>>(out);
}